// round 2
// baseline (speedup 1.0000x reference)
#include <cuda_runtime.h>

#define CB 8
#define CL 1024
#define CH 8
#define CE 64
#define CHIST 512
#define ROWSTRIDE (CH*CE)   /* 512 floats between consecutive l */
#define SCALE 0.125f
#define NEG_BIG (-1e30f)

// Flash-style causal attention, fp32, 64x64 tiles.
// Warp w owns query rows [8w, 8w+8) in all phases (score tile is warp-private).
__global__ void __launch_bounds__(256, 2)
attn_kernel(const float* __restrict__ gq,  const float* __restrict__ gk,
            const float* __restrict__ gv,  const float* __restrict__ gqd,
            const float* __restrict__ gkd, const float* __restrict__ gvd,
            float* __restrict__ gout)
{
    extern __shared__ float smem[];
    float* Qt = smem;           // [e][64] transposed + e4-XOR swizzled
    float* Kt = smem + 4096;    // [e][64] transposed + e4-XOR swizzled
    float* Vs = smem + 8192;    // [s][64] natural
    float* Sm = smem + 12288;   // [r][64] scores -> probabilities

    const int qt = blockIdx.x;          // query tile 0..15
    const int h  = blockIdx.y;
    const int b  = blockIdx.z;
    const int q0 = qt << 6;

    const int t    = threadIdx.x;
    const int lane = t & 31;
    const int w    = t >> 5;            // warp 0..7
    const int ty   = t >> 4;            // 0..15 (rows ty*4..+3)
    const int tx   = t & 15;            // 0..15 (cols tx*4..+3)

    const size_t bh = (size_t)b * CL * ROWSTRIDE + (size_t)h * CE;

    // ---- load Q tile (q_eff row select), transposed + swizzled ----
    #pragma unroll
    for (int i = 0; i < 4; i++) {
        int fidx = t + (i << 8);
        int c  = fidx >> 4;             // local row 0..63
        int e4 = fidx & 15;
        int gl = q0 + c;
        const float* src = (gl < CHIST ? gq : gqd) + bh + (size_t)gl * ROWSTRIDE + (e4 << 2);
        float4 val = *(const float4*)src;
        int col = (((c >> 2) ^ e4) << 2) | (c & 3);
        Qt[(e4*4+0)*64 + col] = val.x;
        Qt[(e4*4+1)*64 + col] = val.y;
        Qt[(e4*4+2)*64 + col] = val.z;
        Qt[(e4*4+3)*64 + col] = val.w;
    }

    float acc0[8], acc1[8], mrow[8], lrow[8];
    #pragma unroll
    for (int i = 0; i < 8; i++) { acc0[i]=0.f; acc1[i]=0.f; mrow[i]=NEG_BIG; lrow[i]=0.f; }

    for (int st = 0; st <= qt; ++st) {
        const int s0 = st << 6;
        const bool diag = (st == qt);

        __syncthreads();  // previous iteration's consumers done before overwrite
        // ---- load K (transposed+swizzled) and V (natural) ----
        #pragma unroll
        for (int i = 0; i < 4; i++) {
            int fidx = t + (i << 8);
            int c  = fidx >> 4;
            int e4 = fidx & 15;
            const float* ksrc = gk + bh + (size_t)(s0 + c) * ROWSTRIDE + (e4 << 2);
            float4 kv = *(const float4*)ksrc;
            int col = (((c >> 2) ^ e4) << 2) | (c & 3);
            Kt[(e4*4+0)*64 + col] = kv.x;
            Kt[(e4*4+1)*64 + col] = kv.y;
            Kt[(e4*4+2)*64 + col] = kv.z;
            Kt[(e4*4+3)*64 + col] = kv.w;
            const float* vsrc = gv + bh + (size_t)(s0 + c) * ROWSTRIDE + (e4 << 2);
            *(float4*)&Vs[c*64 + (e4 << 2)] = *(const float4*)vsrc;
        }
        __syncthreads();

        // ---- Phase A: 4x4 register-blocked S = Q K^T ----
        float s00[4][4];
        #pragma unroll
        for (int i = 0; i < 4; i++)
            #pragma unroll
            for (int j = 0; j < 4; j++) s00[i][j] = 0.f;

        #pragma unroll 4
        for (int e4 = 0; e4 < 16; e4++) {
            const float* qb = &Qt[(e4 << 2)*64 + ((ty ^ e4) << 2)];
            const float* kb = &Kt[(e4 << 2)*64 + ((tx ^ e4) << 2)];
            #pragma unroll
            for (int kk = 0; kk < 4; kk++) {
                float4 qv = *(const float4*)(qb + kk*64);
                float4 kv = *(const float4*)(kb + kk*64);
                s00[0][0] += qv.x*kv.x; s00[0][1] += qv.x*kv.y; s00[0][2] += qv.x*kv.z; s00[0][3] += qv.x*kv.w;
                s00[1][0] += qv.y*kv.x; s00[1][1] += qv.y*kv.y; s00[1][2] += qv.y*kv.z; s00[1][3] += qv.y*kv.w;
                s00[2][0] += qv.z*kv.x; s00[2][1] += qv.z*kv.y; s00[2][2] += qv.z*kv.z; s00[2][3] += qv.z*kv.w;
                s00[3][0] += qv.w*kv.x; s00[3][1] += qv.w*kv.y; s00[3][2] += qv.w*kv.z; s00[3][3] += qv.w*kv.w;
            }
        }

        // scale + causal mask (diag tile only) + store
        #pragma unroll
        for (int i = 0; i < 4; i++) {
            int r = (ty << 2) + i;
            float4 sv;
            sv.x = s00[i][0]*SCALE; sv.y = s00[i][1]*SCALE;
            sv.z = s00[i][2]*SCALE; sv.w = s00[i][3]*SCALE;
            if (diag) {
                int c0 = tx << 2;
                if (c0 + 0 > r) sv.x = NEG_BIG;
                if (c0 + 1 > r) sv.y = NEG_BIG;
                if (c0 + 2 > r) sv.z = NEG_BIG;
                if (c0 + 3 > r) sv.w = NEG_BIG;
            }
            *(float4*)&Sm[r*64 + (tx << 2)] = sv;
        }

        // ---- diagonal score override (drawn q/k) for l >= HIST ----
        if (diag && q0 >= CHIST) {
            __syncthreads();
            if (t < 64) {
                int gl = q0 + t;
                const float* qrow = gqd + bh + (size_t)gl * ROWSTRIDE;
                const float* krow = gkd + bh + (size_t)gl * ROWSTRIDE;
                float dot = 0.f;
                #pragma unroll
                for (int e4 = 0; e4 < 16; e4++) {
                    float4 a = *(const float4*)(qrow + (e4 << 2));
                    float4 c2 = *(const float4*)(krow + (e4 << 2));
                    dot += a.x*c2.x + a.y*c2.y + a.z*c2.z + a.w*c2.w;
                }
                Sm[t*64 + t] = dot * SCALE;
            }
            __syncthreads();
        }
        __syncwarp();

        // ---- Phase B: online softmax (warp-private rows) ----
        #pragma unroll
        for (int i = 0; i < 8; i++) {
            const int r = (w << 3) + i;
            float sv0 = Sm[r*64 + lane];
            float sv1 = Sm[r*64 + 32 + lane];
            float tmax = fmaxf(sv0, sv1);
            #pragma unroll
            for (int off = 16; off > 0; off >>= 1)
                tmax = fmaxf(tmax, __shfl_xor_sync(0xffffffffu, tmax, off));
            float mnew = fmaxf(mrow[i], tmax);
            float corr = __expf(mrow[i] - mnew);
            float p0 = __expf(sv0 - mnew);
            float p1 = __expf(sv1 - mnew);
            float ps = p0 + p1;
            #pragma unroll
            for (int off = 16; off > 0; off >>= 1)
                ps += __shfl_xor_sync(0xffffffffu, ps, off);
            lrow[i] = lrow[i]*corr + ps;
            mrow[i] = mnew;
            acc0[i] *= corr; acc1[i] *= corr;
            Sm[r*64 + lane]      = p0;
            Sm[r*64 + 32 + lane] = p1;
        }
        __syncwarp();

        // ---- Phase C: acc += P V (lane owns cols lane, lane+32) ----
        #pragma unroll 4
        for (int j4 = 0; j4 < 16; j4++) {
            float va[4], vb[4];
            #pragma unroll
            for (int kk = 0; kk < 4; kk++) {
                va[kk] = Vs[(j4*4 + kk)*64 + lane];
                vb[kk] = Vs[(j4*4 + kk)*64 + 32 + lane];
            }
            #pragma unroll
            for (int i = 0; i < 8; i++) {
                float4 p = *(const float4*)&Sm[((w << 3) + i)*64 + (j4 << 2)];
                acc0[i] += p.x*va[0]; acc0[i] += p.y*va[1];
                acc0[i] += p.z*va[2]; acc0[i] += p.w*va[3];
                acc1[i] += p.x*vb[0]; acc1[i] += p.y*vb[1];
                acc1[i] += p.z*vb[2]; acc1[i] += p.w*vb[3];
            }
        }

        // ---- diagonal value substitution: acc += p_diag * (vd - v) ----
        if (diag && q0 >= CHIST) {
            #pragma unroll
            for (int i = 0; i < 8; i++) {
                int r = (w << 3) + i;
                int gl = q0 + r;
                float pd = Sm[r*64 + r];
                const float* vdrow = gvd + bh + (size_t)gl * ROWSTRIDE;
                float d0 = vdrow[lane]      - Vs[r*64 + lane];
                float d1 = vdrow[32 + lane] - Vs[r*64 + 32 + lane];
                acc0[i] += pd * d0;
                acc1[i] += pd * d1;
            }
        }
    }

    // ---- epilogue: normalize + store ----
    #pragma unroll
    for (int i = 0; i < 8; i++) {
        int r = (w << 3) + i;
        int gl = q0 + r;
        float inv = 1.f / lrow[i];
        float* o = gout + bh + (size_t)gl * ROWSTRIDE;
        o[lane]      = acc0[i]*inv;
        o[32 + lane] = acc1[i]*inv;
    }
}

extern "C" void kernel_launch(void* const* d_in, const int* in_sizes, int n_in,
                              void* d_out, int out_size)
{
    const float* q  = (const float*)d_in[0];
    const float* k  = (const float*)d_in[1];
    const float* v  = (const float*)d_in[2];
    const float* qd = (const float*)d_in[3];
    const float* kd = (const float*)d_in[4];
    const float* vd = (const float*)d_in[5];
    float* out = (float*)d_out;

    const int smem_bytes = 64 * 1024;
    cudaFuncSetAttribute(attn_kernel, cudaFuncAttributeMaxDynamicSharedMemorySize, smem_bytes);

    dim3 grid(CL / 64, CH, CB);   // (16, 8, 8): qtile fastest -> same (b,h) K/V tiles hot in L2
    attn_kernel<<<grid, 256, smem_bytes>>>(q, k, v, qd, kd, vd, out);
}

// round 7
// speedup vs baseline: 1.0168x; 1.0168x over previous
#include <cuda_runtime.h>

#define CB 8
#define CL 1024
#define CH 8
#define CE 64
#define CHIST 512
#define ROWSTRIDE (CH*CE)   /* 512 floats between consecutive l */
#define SCALE 0.125f
#define NEG_BIG (-1e30f)

// Flash-style causal attention, fp32, 64x64 tiles.
// Warp w owns query rows [8w, 8w+8) in all phases (score tile is warp-private).
__global__ void __launch_bounds__(256, 2)
attn_kernel(const float* __restrict__ gq,  const float* __restrict__ gk,
            const float* __restrict__ gv,  const float* __restrict__ gqd,
            const float* __restrict__ gkd, const float* __restrict__ gvd,
            float* __restrict__ gout)
{
    extern __shared__ float smem[];
    float* Qt = smem;           // [e][64] transposed + e4-XOR swizzled
    float* Kt = smem + 4096;    // [e][64] transposed + e4-XOR swizzled
    float* Vs = smem + 8192;    // [s][64] natural
    float* Sm = smem + 12288;   // [r][64] scores -> probabilities

    const int qt = blockIdx.x;          // query tile 0..15
    const int h  = blockIdx.y;
    const int b  = blockIdx.z;
    const int q0 = qt << 6;

    const int t    = threadIdx.x;
    const int lane = t & 31;
    const int w    = t >> 5;            // warp 0..7
    const int ty   = t >> 4;            // 0..15 (rows ty*4..+3)
    const int tx   = t & 15;            // 0..15 (cols tx*4..+3)

    const size_t bh = (size_t)b * CL * ROWSTRIDE + (size_t)h * CE;

    // ---- load Q tile (q_eff row select), transposed + swizzled ----
    #pragma unroll
    for (int i = 0; i < 4; i++) {
        int fidx = t + (i << 8);
        int c  = fidx >> 4;             // local row 0..63
        int e4 = fidx & 15;
        int gl = q0 + c;
        const float* src = (gl < CHIST ? gq : gqd) + bh + (size_t)gl * ROWSTRIDE + (e4 << 2);
        float4 val = *(const float4*)src;
        int col = (((c >> 2) ^ e4) << 2) | (c & 3);
        Qt[(e4*4+0)*64 + col] = val.x;
        Qt[(e4*4+1)*64 + col] = val.y;
        Qt[(e4*4+2)*64 + col] = val.z;
        Qt[(e4*4+3)*64 + col] = val.w;
    }

    float acc0[8], acc1[8], mrow[8], lrow[8];
    #pragma unroll
    for (int i = 0; i < 8; i++) { acc0[i]=0.f; acc1[i]=0.f; mrow[i]=NEG_BIG; lrow[i]=0.f; }

    for (int st = 0; st <= qt; ++st) {
        const int s0 = st << 6;
        const bool diag = (st == qt);

        __syncthreads();  // previous iteration's consumers done before overwrite
        // ---- load K (transposed+swizzled) and V (natural) ----
        #pragma unroll
        for (int i = 0; i < 4; i++) {
            int fidx = t + (i << 8);
            int c  = fidx >> 4;
            int e4 = fidx & 15;
            const float* ksrc = gk + bh + (size_t)(s0 + c) * ROWSTRIDE + (e4 << 2);
            float4 kv = *(const float4*)ksrc;
            int col = (((c >> 2) ^ e4) << 2) | (c & 3);
            Kt[(e4*4+0)*64 + col] = kv.x;
            Kt[(e4*4+1)*64 + col] = kv.y;
            Kt[(e4*4+2)*64 + col] = kv.z;
            Kt[(e4*4+3)*64 + col] = kv.w;
            const float* vsrc = gv + bh + (size_t)(s0 + c) * ROWSTRIDE + (e4 << 2);
            *(float4*)&Vs[c*64 + (e4 << 2)] = *(const float4*)vsrc;
        }
        __syncthreads();

        // ---- Phase A: 4x4 register-blocked S = Q K^T ----
        float s00[4][4];
        #pragma unroll
        for (int i = 0; i < 4; i++)
            #pragma unroll
            for (int j = 0; j < 4; j++) s00[i][j] = 0.f;

        #pragma unroll 4
        for (int e4 = 0; e4 < 16; e4++) {
            const float* qb = &Qt[(e4 << 2)*64 + ((ty ^ e4) << 2)];
            const float* kb = &Kt[(e4 << 2)*64 + ((tx ^ e4) << 2)];
            #pragma unroll
            for (int kk = 0; kk < 4; kk++) {
                float4 qv = *(const float4*)(qb + kk*64);
                float4 kv = *(const float4*)(kb + kk*64);
                s00[0][0] += qv.x*kv.x; s00[0][1] += qv.x*kv.y; s00[0][2] += qv.x*kv.z; s00[0][3] += qv.x*kv.w;
                s00[1][0] += qv.y*kv.x; s00[1][1] += qv.y*kv.y; s00[1][2] += qv.y*kv.z; s00[1][3] += qv.y*kv.w;
                s00[2][0] += qv.z*kv.x; s00[2][1] += qv.z*kv.y; s00[2][2] += qv.z*kv.z; s00[2][3] += qv.z*kv.w;
                s00[3][0] += qv.w*kv.x; s00[3][1] += qv.w*kv.y; s00[3][2] += qv.w*kv.z; s00[3][3] += qv.w*kv.w;
            }
        }

        // scale + causal mask (diag tile only) + store
        #pragma unroll
        for (int i = 0; i < 4; i++) {
            int r = (ty << 2) + i;
            float4 sv;
            sv.x = s00[i][0]*SCALE; sv.y = s00[i][1]*SCALE;
            sv.z = s00[i][2]*SCALE; sv.w = s00[i][3]*SCALE;
            if (diag) {
                int c0 = tx << 2;
                if (c0 + 0 > r) sv.x = NEG_BIG;
                if (c0 + 1 > r) sv.y = NEG_BIG;
                if (c0 + 2 > r) sv.z = NEG_BIG;
                if (c0 + 3 > r) sv.w = NEG_BIG;
            }
            *(float4*)&Sm[r*64 + (tx << 2)] = sv;
        }

        // ---- diagonal score override (drawn q/k) for l >= HIST ----
        if (diag && q0 >= CHIST) {
            __syncthreads();
            if (t < 64) {
                int gl = q0 + t;
                const float* qrow = gqd + bh + (size_t)gl * ROWSTRIDE;
                const float* krow = gkd + bh + (size_t)gl * ROWSTRIDE;
                float dot = 0.f;
                #pragma unroll
                for (int e4 = 0; e4 < 16; e4++) {
                    float4 a = *(const float4*)(qrow + (e4 << 2));
                    float4 c2 = *(const float4*)(krow + (e4 << 2));
                    dot += a.x*c2.x + a.y*c2.y + a.z*c2.z + a.w*c2.w;
                }
                Sm[t*64 + t] = dot * SCALE;
            }
            __syncthreads();
        }
        __syncwarp();

        // ---- Phase B: online softmax (warp-private rows) ----
        #pragma unroll
        for (int i = 0; i < 8; i++) {
            const int r = (w << 3) + i;
            float sv0 = Sm[r*64 + lane];
            float sv1 = Sm[r*64 + 32 + lane];
            float tmax = fmaxf(sv0, sv1);
            #pragma unroll
            for (int off = 16; off > 0; off >>= 1)
                tmax = fmaxf(tmax, __shfl_xor_sync(0xffffffffu, tmax, off));
            float mnew = fmaxf(mrow[i], tmax);
            float corr = __expf(mrow[i] - mnew);
            float p0 = __expf(sv0 - mnew);
            float p1 = __expf(sv1 - mnew);
            float ps = p0 + p1;
            #pragma unroll
            for (int off = 16; off > 0; off >>= 1)
                ps += __shfl_xor_sync(0xffffffffu, ps, off);
            lrow[i] = lrow[i]*corr + ps;
            mrow[i] = mnew;
            acc0[i] *= corr; acc1[i] *= corr;
            Sm[r*64 + lane]      = p0;
            Sm[r*64 + 32 + lane] = p1;
        }
        __syncwarp();

        // ---- Phase C: acc += P V (lane owns cols lane, lane+32) ----
        #pragma unroll 4
        for (int j4 = 0; j4 < 16; j4++) {
            float va[4], vb[4];
            #pragma unroll
            for (int kk = 0; kk < 4; kk++) {
                va[kk] = Vs[(j4*4 + kk)*64 + lane];
                vb[kk] = Vs[(j4*4 + kk)*64 + 32 + lane];
            }
            #pragma unroll
            for (int i = 0; i < 8; i++) {
                float4 p = *(const float4*)&Sm[((w << 3) + i)*64 + (j4 << 2)];
                acc0[i] += p.x*va[0]; acc0[i] += p.y*va[1];
                acc0[i] += p.z*va[2]; acc0[i] += p.w*va[3];
                acc1[i] += p.x*vb[0]; acc1[i] += p.y*vb[1];
                acc1[i] += p.z*vb[2]; acc1[i] += p.w*vb[3];
            }
        }

        // ---- diagonal value substitution: acc += p_diag * (vd - v) ----
        if (diag && q0 >= CHIST) {
            #pragma unroll
            for (int i = 0; i < 8; i++) {
                int r = (w << 3) + i;
                int gl = q0 + r;
                float pd = Sm[r*64 + r];
                const float* vdrow = gvd + bh + (size_t)gl * ROWSTRIDE;
                float d0 = vdrow[lane]      - Vs[r*64 + lane];
                float d1 = vdrow[32 + lane] - Vs[r*64 + 32 + lane];
                acc0[i] += pd * d0;
                acc1[i] += pd * d1;
            }
        }
    }

    // ---- epilogue: normalize + store ----
    #pragma unroll
    for (int i = 0; i < 8; i++) {
        int r = (w << 3) + i;
        int gl = q0 + r;
        float inv = 1.f / lrow[i];
        float* o = gout + bh + (size_t)gl * ROWSTRIDE;
        o[lane]      = acc0[i]*inv;
        o[32 + lane] = acc1[i]*inv;
    }
}

extern "C" void kernel_launch(void* const* d_in, const int* in_sizes, int n_in,
                              void* d_out, int out_size)
{
    const float* q  = (const float*)d_in[0];
    const float* k  = (const float*)d_in[1];
    const float* v  = (const float*)d_in[2];
    const float* qd = (const float*)d_in[3];
    const float* kd = (const float*)d_in[4];
    const float* vd = (const float*)d_in[5];
    float* out = (float*)d_out;

    const int smem_bytes = 64 * 1024;
    cudaFuncSetAttribute(attn_kernel, cudaFuncAttributeMaxDynamicSharedMemorySize, smem_bytes);

    dim3 grid(CL / 64, CH, CB);   // (16, 8, 8): qtile fastest -> same (b,h) K/V tiles hot in L2
    attn_kernel<<<grid, 256, smem_bytes>>>(q, k, v, qd, kd, vd, out);
}

// round 11
// speedup vs baseline: 2.1157x; 2.0807x over previous
#include <cuda_runtime.h>

#define CB 8
#define CH 8
#define CL 1024
#define CE 64
#define RS 512                    /* floats between consecutive l in [b,l,h,e] */
#define BSTR (CL*RS)
#define SCL2E 0.1803368801111204f /* 0.125 * log2(e) */
#define KST 68                    /* K/P smem row stride (floats) */
#define VST 72                    /* V smem row stride (floats) */

// Repacked blobs [bh(64)][l(1024)][e(64)], tf32-rounded
__device__ float g_kh[64*1024*64];
__device__ float g_kl[64*1024*64];
__device__ float g_vr[64*1024*64];

__device__ __forceinline__ float to_tf32(float x){
    float r; asm("cvt.rna.tf32.f32 %0, %1;" : "=f"(r) : "f"(x)); return r;
}
__device__ __forceinline__ float ex2f(float x){
    float r; asm("ex2.approx.ftz.f32 %0, %1;" : "=f"(r) : "f"(x)); return r;
}
__device__ __forceinline__ void cp16(float* dst, const float* src){
    unsigned u = (unsigned)__cvta_generic_to_shared(dst);
    asm volatile("cp.async.ca.shared.global [%0], [%1], 16;" :: "r"(u), "l"(src) : "memory");
}
__device__ __forceinline__ void mma8(float* d, const unsigned* a, unsigned b0, unsigned b1){
    asm volatile("mma.sync.aligned.m16n8k8.row.col.f32.tf32.tf32.f32 "
        "{%0,%1,%2,%3}, {%4,%5,%6,%7}, {%8,%9}, {%0,%1,%2,%3};"
        : "+f"(d[0]), "+f"(d[1]), "+f"(d[2]), "+f"(d[3])
        : "r"(a[0]), "r"(a[1]), "r"(a[2]), "r"(a[3]), "r"(b0), "r"(b1));
}

// ---------------------------------------------------------------- prepass
// K -> tf32 hi/lo blobs, V -> tf32-rounded blob, repacked [bh][l][64]
__global__ void __launch_bounds__(256) prep(const float* __restrict__ gk,
                                            const float* __restrict__ gv)
{
    unsigned idx = blockIdx.x * 256u + threadIdx.x;   // 2*1048576 total
    unsigned which = idx >> 20;
    unsigned o = idx & 0xFFFFFu;                       // [bh][l][e4]
    unsigned e4 = o & 15u, l = (o >> 4) & 1023u, bh = o >> 14;
    unsigned b = bh >> 3, h = bh & 7u;
    const float* src = (which ? gv : gk) + (size_t)b*BSTR + (size_t)l*RS + h*CE + e4*4;
    float4 v = *(const float4*)src;
    if (which){
        float4 r;
        r.x = to_tf32(v.x); r.y = to_tf32(v.y); r.z = to_tf32(v.z); r.w = to_tf32(v.w);
        ((float4*)g_vr)[o] = r;
    } else {
        float4 hi, lo;
        hi.x = to_tf32(v.x); lo.x = to_tf32(v.x - hi.x);
        hi.y = to_tf32(v.y); lo.y = to_tf32(v.y - hi.y);
        hi.z = to_tf32(v.z); lo.z = to_tf32(v.z - hi.z);
        hi.w = to_tf32(v.w); lo.w = to_tf32(v.w - hi.w);
        ((float4*)g_kh)[o] = hi;
        ((float4*)g_kl)[o] = lo;
    }
}

// ---------------------------------------------------------------- main
// CTA = 64 q-rows of one (b,h); 4 warps, warp w owns rows 16w..16w+15.
__global__ void __launch_bounds__(128, 2)
attn_main(const float* __restrict__ gq,  const float* __restrict__ gqd,
          const float* __restrict__ gkd, const float* __restrict__ gv,
          const float* __restrict__ gvd, float* __restrict__ gout)
{
    extern __shared__ float sm[];
    float* Kh = sm;                       // [64][KST]
    float* Kl = sm + 64*KST;              // [64][KST]
    float* Vv = sm + 2*64*KST;            // [64][VST]
    float* Pq = sm + 2*64*KST + 64*VST;   // [64][KST]  (Q staging, then P)

    const int t = threadIdx.x, w = t >> 5, lane = t & 31;
    const int g = lane >> 2, c4 = lane & 3;
    const int bx = blockIdx.x;
    const int qt = 15 - (bx >> 6);        // heaviest CTAs first (LPT)
    const int bh = bx & 63;
    const int b = bh >> 3, h = bh & 7;
    const int q0 = qt << 6, n = qt + 1;
    const bool drawn = (qt >= 8);
    const int rA = (w << 4) + g;          // local row A; row B = rA + 8
    const size_t hb = (size_t)b*BSTR + h*CE;
    const size_t kbase = (size_t)bh * (1024*64);

    // ---- Q -> Pq (staging) ----
    const float* qsrc = drawn ? gqd : gq;
    #pragma unroll
    for (int it = 0; it < 8; it++){
        int u = it*128 + t;
        int e4 = u & 15, r = u >> 4;
        float4 val = *(const float4*)(qsrc + hb + (size_t)(q0 + r)*RS + e4*4);
        *(float4*)&Pq[r*KST + e4*4] = val;
    }
    __syncthreads();

    // ---- Q fragments (hi/lo tf32), persistent ----
    unsigned qh[8][4], ql[8][4];
    #pragma unroll
    for (int kk = 0; kk < 8; kk++){
        float a0 = Pq[rA*KST     + kk*8 + c4];
        float a1 = Pq[(rA+8)*KST + kk*8 + c4];
        float a2 = Pq[rA*KST     + kk*8 + c4 + 4];
        float a3 = Pq[(rA+8)*KST + kk*8 + c4 + 4];
        float h0 = to_tf32(a0), h1 = to_tf32(a1), h2 = to_tf32(a2), h3 = to_tf32(a3);
        qh[kk][0] = __float_as_uint(h0); ql[kk][0] = __float_as_uint(to_tf32(a0 - h0));
        qh[kk][1] = __float_as_uint(h1); ql[kk][1] = __float_as_uint(to_tf32(a1 - h1));
        qh[kk][2] = __float_as_uint(h2); ql[kk][2] = __float_as_uint(to_tf32(a2 - h2));
        qh[kk][3] = __float_as_uint(h3); ql[kk][3] = __float_as_uint(to_tf32(a3 - h3));
    }

    // ---- drawn-diagonal logits (fp32, full precision) ----
    float dl0 = 0.f, dl1 = 0.f;
    const size_t r0off = hb + (size_t)(q0 + rA)*RS;
    const size_t r1off = hb + (size_t)(q0 + rA + 8)*RS;
    if (drawn){
        float s0 = 0.f, s1 = 0.f;
        #pragma unroll
        for (int e = 0; e < 16; e++){
            float4 a = *(const float4*)(gqd + r0off + e*4);
            float4 c = *(const float4*)(gkd + r0off + e*4);
            s0 += a.x*c.x + a.y*c.y + a.z*c.z + a.w*c.w;
            float4 a1 = *(const float4*)(gqd + r1off + e*4);
            float4 c1 = *(const float4*)(gkd + r1off + e*4);
            s1 += a1.x*c1.x + a1.y*c1.y + a1.z*c1.z + a1.w*c1.w;
        }
        dl0 = s0 * SCL2E; dl1 = s1 * SCL2E;
    }

    float O[8][4];
    #pragma unroll
    for (int nt = 0; nt < 8; nt++){ O[nt][0]=0.f; O[nt][1]=0.f; O[nt][2]=0.f; O[nt][3]=0.f; }
    float ls0 = 0.f, ls1 = 0.f, pd0 = 0.f, pd1 = 0.f;

    for (int st = 0; st < n; st++){
        __syncthreads();   // previous tile fully consumed
        const size_t soff = kbase + (size_t)(st*64)*64;
        #pragma unroll
        for (int j = 0; j < 24; j++){
            int u = j*128 + t;
            int which = u >> 10, o = u & 1023, r = o >> 4, e4 = o & 15;
            const float* src = (which == 0 ? g_kh : which == 1 ? g_kl : g_vr) + soff + r*64 + e4*4;
            float* dst = (which == 2 ? Vv + r*VST : (which == 0 ? Kh : Kl) + r*KST) + e4*4;
            cp16(dst, src);
        }
        asm volatile("cp.async.commit_group;\n\tcp.async.wait_group 0;" ::: "memory");
        __syncthreads();

        const bool diag = (st == qt);
        float sA = 0.f, sB = 0.f;

        // ---- QK (3-pass hi/lo) + softmax per 8-col tile ----
        #pragma unroll
        for (int nt = 0; nt < 8; nt++){
            float C[4] = {0.f, 0.f, 0.f, 0.f};
            #pragma unroll
            for (int kk = 0; kk < 8; kk++){
                const float* kh = &Kh[(nt*8 + g)*KST + kk*8 + c4];
                const float* kl = &Kl[(nt*8 + g)*KST + kk*8 + c4];
                unsigned b0h = __float_as_uint(kh[0]), b1h = __float_as_uint(kh[4]);
                unsigned b0l = __float_as_uint(kl[0]), b1l = __float_as_uint(kl[4]);
                mma8(C, qh[kk], b0h, b1h);
                mma8(C, ql[kk], b0h, b1h);
                mma8(C, qh[kk], b0l, b1l);
            }
            float p0, p1, p2, p3;
            const int col0 = nt*8 + 2*c4, col1 = col0 + 1;
            if (diag){
                float x0 = C[0]*SCL2E, x1 = C[1]*SCL2E, x2 = C[2]*SCL2E, x3 = C[3]*SCL2E;
                if (drawn){
                    if (col0 == rA)     x0 = dl0;
                    if (col1 == rA)     x1 = dl0;
                    if (col0 == rA + 8) x2 = dl1;
                    if (col1 == rA + 8) x3 = dl1;
                }
                p0 = (col0 > rA)     ? 0.f : to_tf32(ex2f(x0));
                p1 = (col1 > rA)     ? 0.f : to_tf32(ex2f(x1));
                p2 = (col0 > rA + 8) ? 0.f : to_tf32(ex2f(x2));
                p3 = (col1 > rA + 8) ? 0.f : to_tf32(ex2f(x3));
                if (drawn){
                    if (col0 == rA)     pd0 = p0;
                    if (col1 == rA)     pd0 = p1;
                    if (col0 == rA + 8) pd1 = p2;
                    if (col1 == rA + 8) pd1 = p3;
                }
            } else {
                p0 = to_tf32(ex2f(C[0]*SCL2E));
                p1 = to_tf32(ex2f(C[1]*SCL2E));
                p2 = to_tf32(ex2f(C[2]*SCL2E));
                p3 = to_tf32(ex2f(C[3]*SCL2E));
            }
            sA += p0 + p1; sB += p2 + p3;
            Pq[rA*KST     + col0] = p0; Pq[rA*KST     + col1] = p1;
            Pq[(rA+8)*KST + col0] = p2; Pq[(rA+8)*KST + col1] = p3;
        }

        // row-sum reduce within 4-lane groups
        sA += __shfl_xor_sync(0xffffffffu, sA, 1);
        sA += __shfl_xor_sync(0xffffffffu, sA, 2);
        sB += __shfl_xor_sync(0xffffffffu, sB, 1);
        sB += __shfl_xor_sync(0xffffffffu, sB, 2);
        ls0 += sA; ls1 += sB;
        if (diag && drawn){
            pd0 += __shfl_xor_sync(0xffffffffu, pd0, 1);
            pd0 += __shfl_xor_sync(0xffffffffu, pd0, 2);
            pd1 += __shfl_xor_sync(0xffffffffu, pd1, 1);
            pd1 += __shfl_xor_sync(0xffffffffu, pd1, 2);
        }
        __syncwarp();   // P rows are warp-private: warp-level fence suffices

        // ---- PV ----
        unsigned pa[8][4];
        #pragma unroll
        for (int kk = 0; kk < 8; kk++){
            pa[kk][0] = __float_as_uint(Pq[rA*KST     + kk*8 + c4]);
            pa[kk][1] = __float_as_uint(Pq[(rA+8)*KST + kk*8 + c4]);
            pa[kk][2] = __float_as_uint(Pq[rA*KST     + kk*8 + c4 + 4]);
            pa[kk][3] = __float_as_uint(Pq[(rA+8)*KST + kk*8 + c4 + 4]);
        }
        #pragma unroll
        for (int nt = 0; nt < 8; nt++){
            #pragma unroll
            for (int kk = 0; kk < 8; kk++){
                const float* vb = &Vv[(kk*8 + c4)*VST + nt*8 + g];
                unsigned b0 = __float_as_uint(vb[0]);
                unsigned b1 = __float_as_uint(vb[4*VST]);
                mma8(O[nt], pa[kk], b0, b1);
            }
        }
        __syncwarp();   // P reads done before next iteration overwrites
    }

    // ---- epilogue: diagonal value substitution + normalize + store ----
    if (drawn){
        #pragma unroll
        for (int nt = 0; nt < 8; nt++){
            int e = nt*8 + 2*c4;
            float2 vd0 = *(const float2*)(gvd + r0off + e);
            float2 v0  = *(const float2*)(gv  + r0off + e);
            O[nt][0] += pd0 * (vd0.x - v0.x);
            O[nt][1] += pd0 * (vd0.y - v0.y);
            float2 vd1 = *(const float2*)(gvd + r1off + e);
            float2 v1  = *(const float2*)(gv  + r1off + e);
            O[nt][2] += pd1 * (vd1.x - v1.x);
            O[nt][3] += pd1 * (vd1.y - v1.y);
        }
    }
    const float i0 = 1.f / ls0, i1 = 1.f / ls1;
    #pragma unroll
    for (int nt = 0; nt < 8; nt++){
        int e = nt*8 + 2*c4;
        float2 o0; o0.x = O[nt][0]*i0; o0.y = O[nt][1]*i0;
        float2 o1; o1.x = O[nt][2]*i1; o1.y = O[nt][3]*i1;
        *(float2*)(gout + r0off + e) = o0;
        *(float2*)(gout + r1off + e) = o1;
    }
}

// ---------------------------------------------------------------- launch
extern "C" void kernel_launch(void* const* d_in, const int* in_sizes, int n_in,
                              void* d_out, int out_size)
{
    const float* q  = (const float*)d_in[0];
    const float* k  = (const float*)d_in[1];
    const float* v  = (const float*)d_in[2];
    const float* qd = (const float*)d_in[3];
    const float* kd = (const float*)d_in[4];
    const float* vd = (const float*)d_in[5];
    float* out = (float*)d_out;

    const int smem_bytes = (2*64*KST + 64*VST + 64*KST) * 4;   // 70,656 B
    cudaFuncSetAttribute(attn_main, cudaFuncAttributeMaxDynamicSharedMemorySize, smem_bytes);

    prep<<<8192, 256>>>(k, v);
    attn_main<<<1024, 128, smem_bytes>>>(q, qd, kd, v, vd, out);
}

// round 13
// speedup vs baseline: 3.4243x; 1.6186x over previous
#include <cuda_runtime.h>

#define CB 8
#define CH 8
#define CL 1024
#define CE 64
#define RS 512                    /* floats between consecutive l in [b,l,h,e] */
#define BSTR (CL*RS)
#define SCL2E 0.1803368801111204f /* 0.125 * log2(e) */
#define KST 68                    /* K/P smem row stride (floats) */
#define VST 72                    /* V smem row stride (floats) */

// Repacked blobs [bh(64)][l(1024)][e(64)], tf32-rounded
__device__ float g_kh[64*1024*64];
__device__ float g_vr[64*1024*64];

__device__ __forceinline__ float to_tf32(float x){
    float r; asm("cvt.rna.tf32.f32 %0, %1;" : "=f"(r) : "f"(x)); return r;
}
__device__ __forceinline__ float ex2f(float x){
    float r; asm("ex2.approx.ftz.f32 %0, %1;" : "=f"(r) : "f"(x)); return r;
}
__device__ __forceinline__ void cp16(float* dst, const float* src){
    unsigned u = (unsigned)__cvta_generic_to_shared(dst);
    asm volatile("cp.async.ca.shared.global [%0], [%1], 16;" :: "r"(u), "l"(src) : "memory");
}
__device__ __forceinline__ void mma8(float* d, const unsigned* a, unsigned b0, unsigned b1){
    asm volatile("mma.sync.aligned.m16n8k8.row.col.f32.tf32.tf32.f32 "
        "{%0,%1,%2,%3}, {%4,%5,%6,%7}, {%8,%9}, {%0,%1,%2,%3};"
        : "+f"(d[0]), "+f"(d[1]), "+f"(d[2]), "+f"(d[3])
        : "r"(a[0]), "r"(a[1]), "r"(a[2]), "r"(a[3]), "r"(b0), "r"(b1));
}

// ---------------------------------------------------------------- prepass
// K -> tf32 blob, V -> tf32 blob, repacked [bh][l][64]
__global__ void __launch_bounds__(256) prep(const float* __restrict__ gk,
                                            const float* __restrict__ gv)
{
    unsigned idx = blockIdx.x * 256u + threadIdx.x;   // 2*1048576 total
    unsigned which = idx >> 20;
    unsigned o = idx & 0xFFFFFu;                       // [bh][l][e4]
    unsigned e4 = o & 15u, l = (o >> 4) & 1023u, bh = o >> 14;
    unsigned b = bh >> 3, h = bh & 7u;
    const float* src = (which ? gv : gk) + (size_t)b*BSTR + (size_t)l*RS + h*CE + e4*4;
    float4 v = *(const float4*)src;
    float4 r;
    r.x = to_tf32(v.x); r.y = to_tf32(v.y); r.z = to_tf32(v.z); r.w = to_tf32(v.w);
    ((float4*)(which ? g_vr : g_kh))[o] = r;
}

// ---------------------------------------------------------------- main
// CTA = 64 q-rows of one (b,h); 4 warps, warp w owns rows 16w..16w+15.
__global__ void __launch_bounds__(128, 3)
attn_main(const float* __restrict__ gq,  const float* __restrict__ gqd,
          const float* __restrict__ gkd, const float* __restrict__ gv,
          const float* __restrict__ gvd, float* __restrict__ gout)
{
    extern __shared__ float sm[];
    float* Kh = sm;                       // [64][KST]
    float* Vv = sm + 64*KST;              // [64][VST]
    float* Pq = sm + 64*KST + 64*VST;     // [64][KST]  (Q staging, then P)

    const int t = threadIdx.x, w = t >> 5, lane = t & 31;
    const int g = lane >> 2, c4 = lane & 3;
    const int bx = blockIdx.x;
    const int qt = 15 - (bx >> 6);        // heaviest CTAs first (LPT)
    const int bh = bx & 63;
    const int b = bh >> 3, h = bh & 7;
    const int q0 = qt << 6, n = qt + 1;
    const bool drawn = (qt >= 8);
    const int rA = (w << 4) + g;          // local row A; row B = rA + 8
    const size_t hb = (size_t)b*BSTR + h*CE;
    const size_t kbase = (size_t)bh * (1024*64);

    // ---- Q -> Pq (staging) ----
    const float* qsrc = drawn ? gqd : gq;
    #pragma unroll
    for (int it = 0; it < 8; it++){
        int u = it*128 + t;
        int e4 = u & 15, r = u >> 4;
        float4 val = *(const float4*)(qsrc + hb + (size_t)(q0 + r)*RS + e4*4);
        *(float4*)&Pq[r*KST + e4*4] = val;
    }
    __syncthreads();

    // ---- Q fragments (tf32), persistent ----
    unsigned qh[8][4];
    #pragma unroll
    for (int kk = 0; kk < 8; kk++){
        qh[kk][0] = __float_as_uint(to_tf32(Pq[rA*KST     + kk*8 + c4]));
        qh[kk][1] = __float_as_uint(to_tf32(Pq[(rA+8)*KST + kk*8 + c4]));
        qh[kk][2] = __float_as_uint(to_tf32(Pq[rA*KST     + kk*8 + c4 + 4]));
        qh[kk][3] = __float_as_uint(to_tf32(Pq[(rA+8)*KST + kk*8 + c4 + 4]));
    }

    // ---- drawn-diagonal logits (fp32, full precision) ----
    float dl0 = 0.f, dl1 = 0.f;
    const size_t r0off = hb + (size_t)(q0 + rA)*RS;
    const size_t r1off = hb + (size_t)(q0 + rA + 8)*RS;
    if (drawn){
        float s0 = 0.f, s1 = 0.f;
        #pragma unroll
        for (int e = 0; e < 16; e++){
            float4 a = *(const float4*)(gqd + r0off + e*4);
            float4 c = *(const float4*)(gkd + r0off + e*4);
            s0 += a.x*c.x + a.y*c.y + a.z*c.z + a.w*c.w;
            float4 a1 = *(const float4*)(gqd + r1off + e*4);
            float4 c1 = *(const float4*)(gkd + r1off + e*4);
            s1 += a1.x*c1.x + a1.y*c1.y + a1.z*c1.z + a1.w*c1.w;
        }
        dl0 = s0 * SCL2E; dl1 = s1 * SCL2E;
    }

    float O[8][4];
    #pragma unroll
    for (int nt = 0; nt < 8; nt++){ O[nt][0]=0.f; O[nt][1]=0.f; O[nt][2]=0.f; O[nt][3]=0.f; }
    float ls0 = 0.f, ls1 = 0.f, pd0 = 0.f, pd1 = 0.f;

    for (int st = 0; st < n; st++){
        __syncthreads();   // previous tile fully consumed
        const size_t soff = kbase + (size_t)(st*64)*64;
        #pragma unroll
        for (int j = 0; j < 16; j++){
            int u = j*128 + t;
            int which = u >> 10, o = u & 1023, r = o >> 4, e4 = o & 15;
            const float* src = (which ? g_vr : g_kh) + soff + r*64 + e4*4;
            float* dst = (which ? Vv + r*VST : Kh + r*KST) + e4*4;
            cp16(dst, src);
        }
        asm volatile("cp.async.commit_group;\n\tcp.async.wait_group 0;" ::: "memory");
        __syncthreads();

        const bool diag = (st == qt);
        float sA = 0.f, sB = 0.f;

        // ---- QK (single-pass tf32) + softmax per 8-col tile ----
        #pragma unroll
        for (int nt = 0; nt < 8; nt++){
            float C[4] = {0.f, 0.f, 0.f, 0.f};
            #pragma unroll
            for (int kk = 0; kk < 8; kk++){
                const float* kh = &Kh[(nt*8 + g)*KST + kk*8 + c4];
                mma8(C, qh[kk], __float_as_uint(kh[0]), __float_as_uint(kh[4]));
            }
            float p0, p1, p2, p3;
            const int col0 = nt*8 + 2*c4, col1 = col0 + 1;
            if (diag){
                float x0 = C[0]*SCL2E, x1 = C[1]*SCL2E, x2 = C[2]*SCL2E, x3 = C[3]*SCL2E;
                if (drawn){
                    if (col0 == rA)     x0 = dl0;
                    if (col1 == rA)     x1 = dl0;
                    if (col0 == rA + 8) x2 = dl1;
                    if (col1 == rA + 8) x3 = dl1;
                }
                p0 = (col0 > rA)     ? 0.f : to_tf32(ex2f(x0));
                p1 = (col1 > rA)     ? 0.f : to_tf32(ex2f(x1));
                p2 = (col0 > rA + 8) ? 0.f : to_tf32(ex2f(x2));
                p3 = (col1 > rA + 8) ? 0.f : to_tf32(ex2f(x3));
                if (drawn){
                    if (col0 == rA)     pd0 = p0;
                    if (col1 == rA)     pd0 = p1;
                    if (col0 == rA + 8) pd1 = p2;
                    if (col1 == rA + 8) pd1 = p3;
                }
            } else {
                p0 = to_tf32(ex2f(C[0]*SCL2E));
                p1 = to_tf32(ex2f(C[1]*SCL2E));
                p2 = to_tf32(ex2f(C[2]*SCL2E));
                p3 = to_tf32(ex2f(C[3]*SCL2E));
            }
            sA += p0 + p1; sB += p2 + p3;
            Pq[rA*KST     + col0] = p0; Pq[rA*KST     + col1] = p1;
            Pq[(rA+8)*KST + col0] = p2; Pq[(rA+8)*KST + col1] = p3;
        }

        // row-sum reduce within 4-lane groups
        sA += __shfl_xor_sync(0xffffffffu, sA, 1);
        sA += __shfl_xor_sync(0xffffffffu, sA, 2);
        sB += __shfl_xor_sync(0xffffffffu, sB, 1);
        sB += __shfl_xor_sync(0xffffffffu, sB, 2);
        ls0 += sA; ls1 += sB;
        if (diag && drawn){
            pd0 += __shfl_xor_sync(0xffffffffu, pd0, 1);
            pd0 += __shfl_xor_sync(0xffffffffu, pd0, 2);
            pd1 += __shfl_xor_sync(0xffffffffu, pd1, 1);
            pd1 += __shfl_xor_sync(0xffffffffu, pd1, 2);
        }
        __syncwarp();   // P rows are warp-private: warp-level fence suffices

        // ---- PV ----
        unsigned pa[8][4];
        #pragma unroll
        for (int kk = 0; kk < 8; kk++){
            pa[kk][0] = __float_as_uint(Pq[rA*KST     + kk*8 + c4]);
            pa[kk][1] = __float_as_uint(Pq[(rA+8)*KST + kk*8 + c4]);
            pa[kk][2] = __float_as_uint(Pq[rA*KST     + kk*8 + c4 + 4]);
            pa[kk][3] = __float_as_uint(Pq[(rA+8)*KST + kk*8 + c4 + 4]);
        }
        #pragma unroll
        for (int nt = 0; nt < 8; nt++){
            #pragma unroll
            for (int kk = 0; kk < 8; kk++){
                const float* vb = &Vv[(kk*8 + c4)*VST + nt*8 + g];
                mma8(O[nt], pa[kk], __float_as_uint(vb[0]), __float_as_uint(vb[4*VST]));
            }
        }
        __syncwarp();   // P reads done before next iteration overwrites
    }

    // ---- epilogue: diagonal value substitution + normalize + store ----
    if (drawn){
        #pragma unroll
        for (int nt = 0; nt < 8; nt++){
            int e = nt*8 + 2*c4;
            float2 vd0 = *(const float2*)(gvd + r0off + e);
            float2 v0  = *(const float2*)(gv  + r0off + e);
            O[nt][0] += pd0 * (vd0.x - v0.x);
            O[nt][1] += pd0 * (vd0.y - v0.y);
            float2 vd1 = *(const float2*)(gvd + r1off + e);
            float2 v1  = *(const float2*)(gv  + r1off + e);
            O[nt][2] += pd1 * (vd1.x - v1.x);
            O[nt][3] += pd1 * (vd1.y - v1.y);
        }
    }
    const float i0 = 1.f / ls0, i1 = 1.f / ls1;
    #pragma unroll
    for (int nt = 0; nt < 8; nt++){
        int e = nt*8 + 2*c4;
        float2 o0; o0.x = O[nt][0]*i0; o0.y = O[nt][1]*i0;
        float2 o1; o1.x = O[nt][2]*i1; o1.y = O[nt][3]*i1;
        *(float2*)(gout + r0off + e) = o0;
        *(float2*)(gout + r1off + e) = o1;
    }
}

// ---------------------------------------------------------------- launch
extern "C" void kernel_launch(void* const* d_in, const int* in_sizes, int n_in,
                              void* d_out, int out_size)
{
    const float* q  = (const float*)d_in[0];
    const float* k  = (const float*)d_in[1];
    const float* v  = (const float*)d_in[2];
    const float* qd = (const float*)d_in[3];
    const float* kd = (const float*)d_in[4];
    const float* vd = (const float*)d_in[5];
    float* out = (float*)d_out;

    const int smem_bytes = (64*KST + 64*VST + 64*KST) * 4;   // 53,248 B
    cudaFuncSetAttribute(attn_main, cudaFuncAttributeMaxDynamicSharedMemorySize, smem_bytes);

    prep<<<8192, 256>>>(k, v);
    attn_main<<<1024, 128, smem_bytes>>>(q, qd, kd, v, vd, out);
}